// round 13
// baseline (speedup 1.0000x reference)
#include <cuda_runtime.h>
#include <cuda_bf16.h>
#include <cstdint>
#include <cstddef>

// ---------------------------------------------------------------------------
// Scratch (no allocations allowed -> __device__ globals)
// ---------------------------------------------------------------------------
__device__ float g_h[1024 * 256];     // h = x @ W_in^T + b_in
__device__ float g_pab[1024 * 512];   // [pa | pb], b1 folded into pa

#define DINL __device__ __forceinline__

// ---------------------------------------------------------------------------
// PTX helpers (plain compute_103-safe: no tcgen05)
// ---------------------------------------------------------------------------
DINL uint32_t smem_u32(const void* p) {
    uint32_t a;
    asm("{ .reg .u64 t; cvta.to.shared.u64 t, %1; cvt.u32.u64 %0, t; }"
        : "=r"(a) : "l"(p));
    return a;
}
DINL void ldsm_x4(uint32_t& r0, uint32_t& r1, uint32_t& r2, uint32_t& r3,
                  uint32_t addr) {
    asm volatile("ldmatrix.sync.aligned.m8n8.x4.shared.b16 {%0,%1,%2,%3}, [%4];"
                 : "=r"(r0), "=r"(r1), "=r"(r2), "=r"(r3) : "r"(addr));
}
DINL void mma16816(float* c, const uint32_t* a, uint32_t b0, uint32_t b1) {
    asm volatile(
        "mma.sync.aligned.m16n8k16.row.col.f32.bf16.bf16.f32 "
        "{%0,%1,%2,%3}, {%4,%5,%6,%7}, {%8,%9}, {%0,%1,%2,%3};"
        : "+f"(c[0]), "+f"(c[1]), "+f"(c[2]), "+f"(c[3])
        : "r"(a[0]), "r"(a[1]), "r"(a[2]), "r"(a[3]), "r"(b0), "r"(b1));
}
DINL float silu_f(float z) {
    const float e = __expf(-z);
    return __fdividef(z, 1.0f + e);
}
DINL uint32_t pack_bf(__nv_bfloat16 a, __nv_bfloat16 b) {
    return (uint32_t)__bfloat16_as_ushort(a)
         | ((uint32_t)__bfloat16_as_ushort(b) << 16);
}
// split two fp32 into packed bf16 hi + residual lo fragments
DINL void split2(float x, float y, uint32_t& hi, uint32_t& lo) {
    const __nv_bfloat16 hx = __float2bfloat16(x);
    const __nv_bfloat16 hy = __float2bfloat16(y);
    hi = pack_bf(hx, hy);
    lo = pack_bf(__float2bfloat16(x - __bfloat162float(hx)),
                 __float2bfloat16(y - __bfloat162float(hy)));
}

// ---------------------------------------------------------------------------
// SMEM layout (bytes)
//   W2 tiles: [e][g] bf16, 64 rows x 512B data, pitch 528 (bank stride 4 mod 32)
//   pa/pb:    fp32 rows pitch 1040 B (260 floats, bank stride 4 mod 32)
// ---------------------------------------------------------------------------
static constexpr int W2_PITCH  = 528;
static constexpr int PAB_PITCH = 1040;
static constexpr int OFF_W2HI = 0;
static constexpr int OFF_W2LO = OFF_W2HI + 64 * W2_PITCH;     // 33792
static constexpr int OFF_PA   = OFF_W2LO + 64 * W2_PITCH;     // 67584 (8 rows)
static constexpr int OFF_PB   = OFF_PA + 8 * PAB_PITCH;       // 75904 (16 rows)
static constexpr int SMEM_TOTAL = OFF_PB + 16 * PAB_PITCH;    // 92544 B -> 2 CTAs/SM

// ---------------------------------------------------------------------------
// Prologue GEMM (validated since R7): C = A @ B'^T (+bias)
//   B'[n][k] = B[(n & 255)*ldb + (n>>8)*hi_off + k]
// ---------------------------------------------------------------------------
template <int BM>
__global__ __launch_bounds__(256) void gemm_nt_kernel(
    const float* __restrict__ A, const float* __restrict__ B,
    const float* __restrict__ bias, float* __restrict__ C,
    int M, int N, int K, int ldb, int hi_off, int bias_n)
{
    __shared__ float As[BM][17];
    __shared__ float Bs[64][17];
    constexpr int MI = BM / 16;
    const int t  = threadIdx.x;
    const int n0 = blockIdx.x * 64;
    const int m0 = blockIdx.y * BM;
    const int lr = t >> 2;
    const int lq = (t & 3) * 4;
    const int ty = t >> 4;
    const int tx = t & 15;

    float acc[MI][4];
#pragma unroll
    for (int i = 0; i < MI; ++i)
#pragma unroll
        for (int j = 0; j < 4; ++j) acc[i][j] = 0.0f;

    for (int k0 = 0; k0 < K; k0 += 16) {
        float4 av = make_float4(0.f, 0.f, 0.f, 0.f);
        const bool doA = (lr < BM);
        if (doA)
            av = *(const float4*)(A + (size_t)(m0 + lr) * K + k0 + lq);
        const int nr = n0 + lr;
        float4 bv = *(const float4*)(B + (size_t)(nr & 255) * ldb
                                       + (size_t)(nr >> 8) * hi_off + k0 + lq);
        __syncthreads();
        if (doA) {
            As[lr][lq + 0] = av.x; As[lr][lq + 1] = av.y;
            As[lr][lq + 2] = av.z; As[lr][lq + 3] = av.w;
        }
        Bs[lr][lq + 0] = bv.x; Bs[lr][lq + 1] = bv.y;
        Bs[lr][lq + 2] = bv.z; Bs[lr][lq + 3] = bv.w;
        __syncthreads();
#pragma unroll
        for (int k = 0; k < 16; ++k) {
            float a[MI], bb[4];
#pragma unroll
            for (int i = 0; i < MI; ++i) a[i] = As[ty * MI + i][k];
#pragma unroll
            for (int j = 0; j < 4; ++j) bb[j] = Bs[tx * 4 + j][k];
#pragma unroll
            for (int i = 0; i < MI; ++i)
#pragma unroll
                for (int j = 0; j < 4; ++j) acc[i][j] = fmaf(a[i], bb[j], acc[i][j]);
        }
    }
#pragma unroll
    for (int j = 0; j < 4; ++j) {
        const int n = n0 + tx * 4 + j;
        const float bz = (n < bias_n) ? bias[n] : 0.0f;
#pragma unroll
        for (int i = 0; i < MI; ++i)
            C[(size_t)(m0 + ty * MI + i) * N + n] = acc[i][j] + bz;
    }
}

// ---------------------------------------------------------------------------
// Main fused kernel, m16-per-warp, SOFTWARE-PIPELINED gen/MMA.
// Per CTA: 128 pairs (8 i x 16 j) x 64 e, K=256 as 16 k16-slices.
// Warp w owns i = i0+w; m-rows are the 16 j's (grp, grp+8).
// A[r][k] = silu(pa[i][k] + pb[r][k]);
// m16n8k16 A-frag: a0=(r=l>>2, k=tig*2), a1=(r+8), a2=(k+8), a3=(r+8,k+8).
// Pipeline per slice s: [8 ldsm for s] -> [gen slice s+1 A-frags] ->
// [24 MMAs for s using frags generated last iteration].
// W2 fp32 -> bf16 hi/lo split is done in-kernel during staging.
// ---------------------------------------------------------------------------
__global__ __launch_bounds__(256, 2) void edge_main_mma(
    const float* __restrict__ pab,
    const float* __restrict__ W2,          // fp32 [e][g], 64 x 256
    const float* __restrict__ b2, float* __restrict__ out)
{
    extern __shared__ __align__(16) char smem[];
    const uint32_t sb = smem_u32(smem);
    const int t = threadIdx.x;
    const int w = t >> 5;
    const int l = t & 31;
    const int i0 = blockIdx.x * 8;
    const int j0 = blockIdx.y * 16;
    const int b  = blockIdx.z;

    // ---- stage W2: fp32 -> bf16 hi/lo split into pitch-528 [e][g] tiles ----
    {
#pragma unroll
        for (int it = 0; it < 8; ++it) {
            const int chunk = t + it * 256;          // 2048 chunks of 8 elems
            const int base = chunk * 8;
            const float4 w0 = *(const float4*)(W2 + base);
            const float4 w1 = *(const float4*)(W2 + base + 4);
            uint32_t h0, l0_, h1, l1_, h2, l2_, h3, l3_;
            split2(w0.x, w0.y, h0, l0_);
            split2(w0.z, w0.w, h1, l1_);
            split2(w1.x, w1.y, h2, l2_);
            split2(w1.z, w1.w, h3, l3_);
            const int row = chunk >> 5;              // e
            const int cc  = chunk & 31;              // 16B column chunk
            *(uint4*)(smem + OFF_W2HI + row * W2_PITCH + cc * 16) =
                make_uint4(h0, h1, h2, h3);
            *(uint4*)(smem + OFF_W2LO + row * W2_PITCH + cc * 16) =
                make_uint4(l0_, l1_, l2_, l3_);
        }
    }
    // ---- stage pa (8 x 256 f32) and pb (16 x 256 f32) ----
#pragma unroll
    for (int i = 0; i < 2; ++i) {
        const int idx = t + i * 256, r = idx >> 6, c4 = idx & 63;
        ((float4*)(smem + OFF_PA + r * PAB_PITCH))[c4] =
            ((const float4*)(pab + (size_t)(b * 256 + i0 + r) * 512))[c4];
    }
#pragma unroll
    for (int i = 0; i < 4; ++i) {
        const int idx = t + i * 256, r = idx >> 6, c4 = idx & 63;
        ((float4*)(smem + OFF_PB + r * PAB_PITCH))[c4] =
            ((const float4*)(pab + (size_t)(b * 256 + j0 + r) * 512 + 256))[c4];
    }
    __syncthreads();   // the ONLY barrier

    const int grp = l >> 2;    // 0..7 (m-row / output j-row)
    const int tig = l & 3;     // thread-in-group (k pair selector)

    const float* paW  = (const float*)(smem + OFF_PA + w * PAB_PITCH);
    const float* pbR0 = (const float*)(smem + OFF_PB + grp * PAB_PITCH);
    const float* pbR1 = (const float*)(smem + OFF_PB + (grp + 8) * PAB_PITCH);

    // B ldmatrix lane addressing (validated R9-R12):
    // x4 groups: (e0-7,kLo),(e0-7,kHi),(e8-15,kLo),(e8-15,kHi)
    const int lg = l >> 3;
    const uint32_t bRowPart =
        (uint32_t)(((lg >> 1) * 8 + (l & 7)) * W2_PITCH + (lg & 1) * 16);
    const uint32_t bHiBase = sb + OFF_W2HI + bRowPart;
    const uint32_t bLoBase = sb + OFF_W2LO + bRowPart;

    float acc[8][4];
#pragma unroll
    for (int n = 0; n < 8; ++n)
#pragma unroll
        for (int q = 0; q < 4; ++q) acc[n][q] = 0.0f;

    // A-fragment generator for slice s -> (ah, al)
    auto gen_frags = [&](int s, uint32_t* ah, uint32_t* al) {
        const int kb = s * 16 + tig * 2;
        const float2 paA  = *(const float2*)(paW  + kb);
        const float2 paB  = *(const float2*)(paW  + kb + 8);
        const float2 pb0A = *(const float2*)(pbR0 + kb);
        const float2 pb0B = *(const float2*)(pbR0 + kb + 8);
        const float2 pb1A = *(const float2*)(pbR1 + kb);
        const float2 pb1B = *(const float2*)(pbR1 + kb + 8);
        split2(silu_f(paA.x + pb0A.x), silu_f(paA.y + pb0A.y), ah[0], al[0]);
        split2(silu_f(paA.x + pb1A.x), silu_f(paA.y + pb1A.y), ah[1], al[1]);
        split2(silu_f(paB.x + pb0B.x), silu_f(paB.y + pb0B.y), ah[2], al[2]);
        split2(silu_f(paB.x + pb1B.x), silu_f(paB.y + pb1B.y), ah[3], al[3]);
    };

    // ping-pong A-fragment buffers
    uint32_t ahB[2][4], alB[2][4];
    gen_frags(0, ahB[0], alB[0]);

#pragma unroll 4
    for (int s = 0; s < 16; ++s) {
        const int cur = s & 1, nxt = cur ^ 1;
        const uint32_t kOff = (uint32_t)(s * 32);

        // 1) issue all B ldmatrix for this slice (independent of gen)
        uint32_t bh[4][4], bl[4][4];
#pragma unroll
        for (int nbp = 0; nbp < 4; ++nbp) {
            const uint32_t eOff = (uint32_t)(nbp * 16 * W2_PITCH);
            ldsm_x4(bh[nbp][0], bh[nbp][1], bh[nbp][2], bh[nbp][3],
                    bHiBase + eOff + kOff);
            ldsm_x4(bl[nbp][0], bl[nbp][1], bl[nbp][2], bl[nbp][3],
                    bLoBase + eOff + kOff);
        }

        // 2) generate NEXT slice's A fragments (covers ldsm + tensor latency)
        if (s < 15) gen_frags(s + 1, ahB[nxt], alB[nxt]);

        // 3) 24 MMAs for the CURRENT slice (A-frags ready since last iter)
        const uint32_t* ah = ahB[cur];
        const uint32_t* al = alB[cur];
#pragma unroll
        for (int nbp = 0; nbp < 4; ++nbp) {
            mma16816(acc[2 * nbp],     ah, bh[nbp][0], bh[nbp][1]);
            mma16816(acc[2 * nbp + 1], ah, bh[nbp][2], bh[nbp][3]);
            mma16816(acc[2 * nbp],     al, bh[nbp][0], bh[nbp][1]);
            mma16816(acc[2 * nbp + 1], al, bh[nbp][2], bh[nbp][3]);
            mma16816(acc[2 * nbp],     ah, bl[nbp][0], bl[nbp][1]);
            mma16816(acc[2 * nbp + 1], ah, bl[nbp][2], bl[nbp][3]);
        }
    }

    // ---- epilogue: + b2, direct coalesced stores ----
    {
        const int ec = tig * 2;
        const size_t rowA = ((size_t)(b * 256 + i0 + w) * 256 + j0 + grp);
        float* oA = out + rowA * 64;
        float* oB = oA + 8 * 64;       // grp + 8 along j
#pragma unroll
        for (int nb = 0; nb < 8; ++nb) {
            const int e = nb * 8 + ec;
            const float2 bb = *(const float2*)(b2 + e);
            *(float2*)(oA + e) = make_float2(acc[nb][0] + bb.x, acc[nb][1] + bb.y);
            *(float2*)(oB + e) = make_float2(acc[nb][2] + bb.x, acc[nb][3] + bb.y);
        }
    }
}

// ---------------------------------------------------------------------------
// Launch
// ---------------------------------------------------------------------------
extern "C" void kernel_launch(void* const* d_in, const int* in_sizes, int n_in,
                              void* d_out, int out_size)
{
    (void)in_sizes; (void)n_in; (void)out_size;
    const float* x    = (const float*)d_in[0];
    const float* W_in = (const float*)d_in[1];
    const float* b_in = (const float*)d_in[2];
    const float* W1   = (const float*)d_in[3];
    const float* b1   = (const float*)d_in[4];
    const float* W2   = (const float*)d_in[5];
    const float* b2   = (const float*)d_in[6];
    float* out = (float*)d_out;

    float *hp = nullptr, *pabp = nullptr;
    cudaGetSymbolAddress((void**)&hp,   g_h);
    cudaGetSymbolAddress((void**)&pabp, g_pab);

    // h = x @ W_in^T + b_in          (128 CTAs)
    gemm_nt_kernel<32><<<dim3(4, 32), 256>>>(x, W_in, b_in, hp,
                                             1024, 256, 256, 256, 0, 256);
    // [pa | pb] = h @ [Wa^T | Wb^T]  (256 CTAs), b1 folded into pa
    gemm_nt_kernel<32><<<dim3(8, 32), 256>>>(hp, W1, b1, pabp,
                                             1024, 512, 256, 512, 256, 256);

    cudaFuncSetAttribute(edge_main_mma,
                         cudaFuncAttributeMaxDynamicSharedMemorySize, SMEM_TOTAL);
    edge_main_mma<<<dim3(32, 16, 4), 256, SMEM_TOTAL>>>(pabp, W2, b2, out);
}

// round 14
// speedup vs baseline: 1.2332x; 1.2332x over previous
#include <cuda_runtime.h>
#include <cuda_bf16.h>
#include <cstdint>
#include <cstddef>

// ---------------------------------------------------------------------------
// Scratch (no allocations allowed -> __device__ globals)
// ---------------------------------------------------------------------------
__device__ float g_h[1024 * 256];              // h = x @ W_in^T + b_in
__device__ float g_pab[1024 * 512];            // [pa | pb], b1 folded into pa
__device__ __nv_bfloat16 g_W2hi[64 * 256];     // bf16 split of W2, natural [e][g]
__device__ __nv_bfloat16 g_W2lo[64 * 256];

#define DINL __device__ __forceinline__

// ---------------------------------------------------------------------------
// PTX helpers (plain compute_103-safe: no tcgen05)
// ---------------------------------------------------------------------------
DINL uint32_t smem_u32(const void* p) {
    uint32_t a;
    asm("{ .reg .u64 t; cvta.to.shared.u64 t, %1; cvt.u32.u64 %0, t; }"
        : "=r"(a) : "l"(p));
    return a;
}
DINL void ldsm_x4(uint32_t& r0, uint32_t& r1, uint32_t& r2, uint32_t& r3,
                  uint32_t addr) {
    asm volatile("ldmatrix.sync.aligned.m8n8.x4.shared.b16 {%0,%1,%2,%3}, [%4];"
                 : "=r"(r0), "=r"(r1), "=r"(r2), "=r"(r3) : "r"(addr));
}
DINL void mma16816(float* c, const uint32_t* a, uint32_t b0, uint32_t b1) {
    asm volatile(
        "mma.sync.aligned.m16n8k16.row.col.f32.bf16.bf16.f32 "
        "{%0,%1,%2,%3}, {%4,%5,%6,%7}, {%8,%9}, {%0,%1,%2,%3};"
        : "+f"(c[0]), "+f"(c[1]), "+f"(c[2]), "+f"(c[3])
        : "r"(a[0]), "r"(a[1]), "r"(a[2]), "r"(a[3]), "r"(b0), "r"(b1));
}
DINL float silu_f(float z) {
    const float e = __expf(-z);
    return __fdividef(z, 1.0f + e);
}
DINL uint32_t pack_bf(__nv_bfloat16 a, __nv_bfloat16 b) {
    return (uint32_t)__bfloat16_as_ushort(a)
         | ((uint32_t)__bfloat16_as_ushort(b) << 16);
}
// split two fp32 into packed bf16 hi + residual lo fragments
DINL void split2(float x, float y, uint32_t& hi, uint32_t& lo) {
    const __nv_bfloat16 hx = __float2bfloat16(x);
    const __nv_bfloat16 hy = __float2bfloat16(y);
    hi = pack_bf(hx, hy);
    lo = pack_bf(__float2bfloat16(x - __bfloat162float(hx)),
                 __float2bfloat16(y - __bfloat162float(hy)));
}

// ---------------------------------------------------------------------------
// Prologue GEMM via mma.sync, split-bf16 3-pass (hh, lh, hl).
// C[m][n] = sum_k A[m*K+k] * B'[n][k] + (n<bias_n ? bias[n] : 0)
//   B'[n][k] = B[(n & 255)*ldb + (n>>8)*hi_off + k]
// Tile: BM=64, BN=64, K-chunks of 64 staged+split to smem (pitch 144 B).
// 8 warps as 2(m) x 4(n); warp tile m32 x n16.
// ---------------------------------------------------------------------------
static constexpr int PG_PITCH = 144;                    // 9 x 16B, odd -> conflict-free
static constexpr int PG_AHI = 0;
static constexpr int PG_ALO = PG_AHI + 64 * PG_PITCH;   // 9216
static constexpr int PG_BHI = PG_ALO + 64 * PG_PITCH;   // 18432
static constexpr int PG_BLO = PG_BHI + 64 * PG_PITCH;   // 27648
static constexpr int PG_SMEM = PG_BLO + 64 * PG_PITCH;  // 36864 B (static)

__global__ __launch_bounds__(256) void gemm_mma_nt(
    const float* __restrict__ A, const float* __restrict__ B,
    const float* __restrict__ bias, float* __restrict__ C,
    int M, int N, int K, int ldb, int hi_off, int bias_n)
{
    __shared__ __align__(16) char smem[PG_SMEM];
    const uint32_t sb = smem_u32(smem);
    const int t = threadIdx.x;
    const int w = t >> 5;
    const int l = t & 31;
    const int n0 = blockIdx.x * 64;
    const int m0 = blockIdx.y * 64;
    const int wm = w >> 2;          // 0..1  (m32 tile)
    const int wn = w & 3;           // 0..3  (n16 tile)

    const int grp = l >> 3;         // ldmatrix lane-group (validated R9-R11)
    // A-frag addr: lanes0-7 (m0-7,kLo), 8-15 (m8-15,kLo), 16-23 (m0-7,kHi), 24-31 (m8-15,kHi)
    const uint32_t aOffPart =
        (uint32_t)(((grp & 1) * 8 + (l & 7)) * PG_PITCH + (grp >> 1) * 16);
    // B-frag addr: (n0-7,kLo),(n0-7,kHi),(n8-15,kLo),(n8-15,kHi)
    const uint32_t bOffPart =
        (uint32_t)((wn * 16 + (grp >> 1) * 8 + (l & 7)) * PG_PITCH + (grp & 1) * 16);

    float acc[2][2][4];
#pragma unroll
    for (int mt = 0; mt < 2; ++mt)
#pragma unroll
        for (int nb = 0; nb < 2; ++nb)
#pragma unroll
            for (int q = 0; q < 4; ++q) acc[mt][nb][q] = 0.0f;

    for (int kc = 0; kc < K; kc += 64) {
        if (kc) __syncthreads();
        // ---- stage + split A chunk (64 x 64 fp32) ----
#pragma unroll
        for (int i = 0; i < 4; ++i) {
            const int idx = t + i * 256, r = idx >> 4, c4 = idx & 15;
            const float4 v =
                *(const float4*)(A + (size_t)(m0 + r) * K + kc + c4 * 4);
            uint32_t h0, lo0, h1, lo1;
            split2(v.x, v.y, h0, lo0);
            split2(v.z, v.w, h1, lo1);
            *(uint2*)(smem + PG_AHI + r * PG_PITCH + c4 * 8) = make_uint2(h0, h1);
            *(uint2*)(smem + PG_ALO + r * PG_PITCH + c4 * 8) = make_uint2(lo0, lo1);
        }
        // ---- stage + split B chunk (64 x 64 fp32) ----
#pragma unroll
        for (int i = 0; i < 4; ++i) {
            const int idx = t + i * 256, r = idx >> 4, c4 = idx & 15;
            const int nr = n0 + r;
            const float4 v =
                *(const float4*)(B + (size_t)(nr & 255) * ldb
                                   + (size_t)(nr >> 8) * hi_off + kc + c4 * 4);
            uint32_t h0, lo0, h1, lo1;
            split2(v.x, v.y, h0, lo0);
            split2(v.z, v.w, h1, lo1);
            *(uint2*)(smem + PG_BHI + r * PG_PITCH + c4 * 8) = make_uint2(h0, h1);
            *(uint2*)(smem + PG_BLO + r * PG_PITCH + c4 * 8) = make_uint2(lo0, lo1);
        }
        __syncthreads();

        // ---- 4 k16 slices ----
#pragma unroll
        for (int s = 0; s < 4; ++s) {
            const uint32_t kOff = (uint32_t)(s * 32);
            uint32_t bh[4], bl[4];
            ldsm_x4(bh[0], bh[1], bh[2], bh[3], sb + PG_BHI + bOffPart + kOff);
            ldsm_x4(bl[0], bl[1], bl[2], bl[3], sb + PG_BLO + bOffPart + kOff);
#pragma unroll
            for (int mt = 0; mt < 2; ++mt) {
                const uint32_t aRow =
                    (uint32_t)((wm * 32 + mt * 16) * PG_PITCH) + aOffPart + kOff;
                uint32_t ah[4], al[4];
                ldsm_x4(ah[0], ah[1], ah[2], ah[3], sb + PG_AHI + aRow);
                ldsm_x4(al[0], al[1], al[2], al[3], sb + PG_ALO + aRow);
#pragma unroll
                for (int nb = 0; nb < 2; ++nb) {
                    mma16816(acc[mt][nb], ah, bh[2 * nb], bh[2 * nb + 1]);
                    mma16816(acc[mt][nb], al, bh[2 * nb], bh[2 * nb + 1]);
                    mma16816(acc[mt][nb], ah, bl[2 * nb], bl[2 * nb + 1]);
                }
            }
        }
    }

    // ---- epilogue: + bias, fp32 float2 stores ----
#pragma unroll
    for (int mt = 0; mt < 2; ++mt) {
#pragma unroll
        for (int nb = 0; nb < 2; ++nb) {
            const int n = n0 + wn * 16 + nb * 8 + (l & 3) * 2;
            const float bx = (n     < bias_n) ? bias[n]     : 0.0f;
            const float by = (n + 1 < bias_n) ? bias[n + 1] : 0.0f;
            const int m = m0 + wm * 32 + mt * 16 + (l >> 2);
            *(float2*)(C + (size_t)m * N + n) =
                make_float2(acc[mt][nb][0] + bx, acc[mt][nb][1] + by);
            *(float2*)(C + (size_t)(m + 8) * N + n) =
                make_float2(acc[mt][nb][2] + bx, acc[mt][nb][3] + by);
        }
    }
}

// ---------------------------------------------------------------------------
// W2 hi/lo bf16 split (natural [e][g] layout)
// ---------------------------------------------------------------------------
__global__ void w2split_kernel(const float* __restrict__ W2,
                               __nv_bfloat16* __restrict__ hi,
                               __nv_bfloat16* __restrict__ lo)
{
    const int idx = blockIdx.x * 256 + threadIdx.x;   // 16384
    const float w = W2[idx];
    const __nv_bfloat16 h = __float2bfloat16(w);
    hi[idx] = h;
    lo[idx] = __float2bfloat16(w - __bfloat162float(h));
}

// ---------------------------------------------------------------------------
// Main fused kernel — EXACT R11 (best: main 85.5us).  m32-per-warp.
// Per CTA: 512 pairs (16 i x 16 j) x 64 e, K=256 as 16 k16-slices.
// ---------------------------------------------------------------------------
static constexpr int W2_PITCH  = 528;
static constexpr int PAB_PITCH = 1040;
static constexpr int OFF_W2HI = 0;
static constexpr int OFF_W2LO = OFF_W2HI + 64 * W2_PITCH;     // 33792
static constexpr int OFF_PA   = OFF_W2LO + 64 * W2_PITCH;     // 67584 (16 rows)
static constexpr int OFF_PB   = OFF_PA + 16 * PAB_PITCH;      // 84224 (16 rows)
static constexpr int SMEM_TOTAL = OFF_PB + 16 * PAB_PITCH;    // 100864 B -> 2 CTAs/SM

__global__ __launch_bounds__(256, 2) void edge_main_mma(
    const float* __restrict__ pab,
    const __nv_bfloat16* __restrict__ W2hi_g,
    const __nv_bfloat16* __restrict__ W2lo_g,
    const float* __restrict__ b2, float* __restrict__ out)
{
    extern __shared__ __align__(16) char smem[];
    const uint32_t sb = smem_u32(smem);
    const int t = threadIdx.x;
    const int w = t >> 5;
    const int l = t & 31;
    const int i0 = blockIdx.x * 16;
    const int j0 = blockIdx.y * 16;
    const int b  = blockIdx.z;

    // ---- stage W2 hi/lo into [e][g] pitch-528 tiles ----
    {
        const uint4* hs = (const uint4*)W2hi_g;   // 2048 uint4 each
        const uint4* ls = (const uint4*)W2lo_g;
#pragma unroll
        for (int i = 0; i < 8; ++i) {
            const int idx = t + i * 256;
            const int row = idx >> 5, c = idx & 31;
            *(uint4*)(smem + OFF_W2HI + row * W2_PITCH + c * 16) = hs[idx];
            *(uint4*)(smem + OFF_W2LO + row * W2_PITCH + c * 16) = ls[idx];
        }
    }
    // ---- stage pa (16 x 256 f32) and pb (16 x 256 f32) ----
#pragma unroll
    for (int i = 0; i < 4; ++i) {
        const int idx = t + i * 256, r = idx >> 6, c4 = idx & 63;
        ((float4*)(smem + OFF_PA + r * PAB_PITCH))[c4] =
            ((const float4*)(pab + (size_t)(b * 256 + i0 + r) * 512))[c4];
    }
#pragma unroll
    for (int i = 0; i < 4; ++i) {
        const int idx = t + i * 256, r = idx >> 6, c4 = idx & 63;
        ((float4*)(smem + OFF_PB + r * PAB_PITCH))[c4] =
            ((const float4*)(pab + (size_t)(b * 256 + j0 + r) * 512 + 256))[c4];
    }
    __syncthreads();   // the ONLY barrier

    const int grp = l >> 2;    // 0..7 (m-row within tile / output j-row)
    const int tig = l & 3;     // thread-in-group (k pair selector)

    const float* paW0 = (const float*)(smem + OFF_PA + w * PAB_PITCH);
    const float* paW1 = (const float*)(smem + OFF_PA + (w + 8) * PAB_PITCH);
    const float* pbR0 = (const float*)(smem + OFF_PB + grp * PAB_PITCH);
    const float* pbR1 = (const float*)(smem + OFF_PB + (grp + 8) * PAB_PITCH);

    // B ldmatrix lane addressing (validated R9-R11)
    const int lg = l >> 3;
    const uint32_t bRowPart =
        (uint32_t)(((lg >> 1) * 8 + (l & 7)) * W2_PITCH + (lg & 1) * 16);
    const uint32_t bHiBase = sb + OFF_W2HI + bRowPart;
    const uint32_t bLoBase = sb + OFF_W2LO + bRowPart;

    float acc0[8][4], acc1[8][4];
#pragma unroll
    for (int n = 0; n < 8; ++n)
#pragma unroll
        for (int q = 0; q < 4; ++q) { acc0[n][q] = 0.0f; acc1[n][q] = 0.0f; }

#pragma unroll 2
    for (int s = 0; s < 16; ++s) {
        const int kb = s * 16 + tig * 2;
        const float2 pb0A = *(const float2*)(pbR0 + kb);
        const float2 pb0B = *(const float2*)(pbR0 + kb + 8);
        const float2 pb1A = *(const float2*)(pbR1 + kb);
        const float2 pb1B = *(const float2*)(pbR1 + kb + 8);

        uint32_t ah0[4], al0[4], ah1[4], al1[4];
        {   // m-tile 0: i = i0 + w
            const float2 paA = *(const float2*)(paW0 + kb);
            const float2 paB = *(const float2*)(paW0 + kb + 8);
            split2(silu_f(paA.x + pb0A.x), silu_f(paA.y + pb0A.y), ah0[0], al0[0]);
            split2(silu_f(paA.x + pb1A.x), silu_f(paA.y + pb1A.y), ah0[1], al0[1]);
            split2(silu_f(paB.x + pb0B.x), silu_f(paB.y + pb0B.y), ah0[2], al0[2]);
            split2(silu_f(paB.x + pb1B.x), silu_f(paB.y + pb1B.y), ah0[3], al0[3]);
        }
        {   // m-tile 1: i = i0 + w + 8
            const float2 paA = *(const float2*)(paW1 + kb);
            const float2 paB = *(const float2*)(paW1 + kb + 8);
            split2(silu_f(paA.x + pb0A.x), silu_f(paA.y + pb0A.y), ah1[0], al1[0]);
            split2(silu_f(paA.x + pb1A.x), silu_f(paA.y + pb1A.y), ah1[1], al1[1]);
            split2(silu_f(paB.x + pb0B.x), silu_f(paB.y + pb0B.y), ah1[2], al1[2]);
            split2(silu_f(paB.x + pb1B.x), silu_f(paB.y + pb1B.y), ah1[3], al1[3]);
        }

        const uint32_t kOff = (uint32_t)(s * 32);
#pragma unroll
        for (int nbp = 0; nbp < 4; ++nbp) {
            const uint32_t eOff = (uint32_t)(nbp * 16 * W2_PITCH);
            uint32_t bh[4], bl[4];
            ldsm_x4(bh[0], bh[1], bh[2], bh[3], bHiBase + eOff + kOff);
            ldsm_x4(bl[0], bl[1], bl[2], bl[3], bLoBase + eOff + kOff);
            mma16816(acc0[2 * nbp],     ah0, bh[0], bh[1]);
            mma16816(acc0[2 * nbp],     al0, bh[0], bh[1]);
            mma16816(acc0[2 * nbp],     ah0, bl[0], bl[1]);
            mma16816(acc0[2 * nbp + 1], ah0, bh[2], bh[3]);
            mma16816(acc0[2 * nbp + 1], al0, bh[2], bh[3]);
            mma16816(acc0[2 * nbp + 1], ah0, bl[2], bl[3]);
            mma16816(acc1[2 * nbp],     ah1, bh[0], bh[1]);
            mma16816(acc1[2 * nbp],     al1, bh[0], bh[1]);
            mma16816(acc1[2 * nbp],     ah1, bl[0], bl[1]);
            mma16816(acc1[2 * nbp + 1], ah1, bh[2], bh[3]);
            mma16816(acc1[2 * nbp + 1], al1, bh[2], bh[3]);
            mma16816(acc1[2 * nbp + 1], ah1, bl[2], bl[3]);
        }
    }

    // ---- epilogue: + b2, direct coalesced stores (4 output rows/thread) ----
    {
        const int ec = tig * 2;
        const size_t row0 = ((size_t)(b * 256 + i0 + w) * 256 + j0 + grp);
        const size_t row1 = ((size_t)(b * 256 + i0 + w + 8) * 256 + j0 + grp);
        float* o0A = out + row0 * 64;
        float* o0B = o0A + 8 * 64;     // grp + 8 along j
        float* o1A = out + row1 * 64;
        float* o1B = o1A + 8 * 64;
#pragma unroll
        for (int nb = 0; nb < 8; ++nb) {
            const int e = nb * 8 + ec;
            const float2 bb = *(const float2*)(b2 + e);
            *(float2*)(o0A + e) = make_float2(acc0[nb][0] + bb.x, acc0[nb][1] + bb.y);
            *(float2*)(o0B + e) = make_float2(acc0[nb][2] + bb.x, acc0[nb][3] + bb.y);
            *(float2*)(o1A + e) = make_float2(acc1[nb][0] + bb.x, acc1[nb][1] + bb.y);
            *(float2*)(o1B + e) = make_float2(acc1[nb][2] + bb.x, acc1[nb][3] + bb.y);
        }
    }
}

// ---------------------------------------------------------------------------
// Launch
// ---------------------------------------------------------------------------
extern "C" void kernel_launch(void* const* d_in, const int* in_sizes, int n_in,
                              void* d_out, int out_size)
{
    (void)in_sizes; (void)n_in; (void)out_size;
    const float* x    = (const float*)d_in[0];
    const float* W_in = (const float*)d_in[1];
    const float* b_in = (const float*)d_in[2];
    const float* W1   = (const float*)d_in[3];
    const float* b1   = (const float*)d_in[4];
    const float* W2   = (const float*)d_in[5];
    const float* b2   = (const float*)d_in[6];
    float* out = (float*)d_out;

    float *hp = nullptr, *pabp = nullptr;
    __nv_bfloat16 *w2hip = nullptr, *w2lop = nullptr;
    cudaGetSymbolAddress((void**)&hp,    g_h);
    cudaGetSymbolAddress((void**)&pabp,  g_pab);
    cudaGetSymbolAddress((void**)&w2hip, g_W2hi);
    cudaGetSymbolAddress((void**)&w2lop, g_W2lo);

    // h = x @ W_in^T + b_in          (64 CTAs, tensor-core)
    gemm_mma_nt<<<dim3(4, 16), 256>>>(x, W_in, b_in, hp,
                                      1024, 256, 256, 256, 0, 256);
    // [pa | pb] = h @ [Wa^T | Wb^T]  (128 CTAs, tensor-core), b1 folded into pa
    gemm_mma_nt<<<dim3(8, 16), 256>>>(hp, W1, b1, pabp,
                                      1024, 512, 256, 512, 256, 256);
    w2split_kernel<<<64, 256>>>(W2, w2hip, w2lop);

    cudaFuncSetAttribute(edge_main_mma,
                         cudaFuncAttributeMaxDynamicSharedMemorySize, SMEM_TOTAL);
    edge_main_mma<<<dim3(16, 16, 4), 256, SMEM_TOTAL>>>(pabp, w2hip, w2lop,
                                                        b2, out);
}

// round 15
// speedup vs baseline: 1.2920x; 1.0477x over previous
#include <cuda_runtime.h>
#include <cuda_bf16.h>
#include <cstdint>
#include <cstddef>

// ---------------------------------------------------------------------------
// Scratch (no allocations allowed -> __device__ globals)
// ---------------------------------------------------------------------------
__device__ float g_h[1024 * 256];              // h = x @ W_in^T + b_in
__device__ float g_pab[1024 * 512];            // [pa | pb], b1 folded into pa
__device__ __nv_bfloat16 g_W2hi[64 * 256];     // bf16 split of W2, natural [e][g]
__device__ __nv_bfloat16 g_W2lo[64 * 256];

#define DINL __device__ __forceinline__

// ---------------------------------------------------------------------------
// PTX helpers (plain compute_103-safe: no tcgen05)
// ---------------------------------------------------------------------------
DINL uint32_t smem_u32(const void* p) {
    uint32_t a;
    asm("{ .reg .u64 t; cvta.to.shared.u64 t, %1; cvt.u32.u64 %0, t; }"
        : "=r"(a) : "l"(p));
    return a;
}
DINL void ldsm_x4(uint32_t& r0, uint32_t& r1, uint32_t& r2, uint32_t& r3,
                  uint32_t addr) {
    asm volatile("ldmatrix.sync.aligned.m8n8.x4.shared.b16 {%0,%1,%2,%3}, [%4];"
                 : "=r"(r0), "=r"(r1), "=r"(r2), "=r"(r3) : "r"(addr));
}
DINL void mma16816(float* c, const uint32_t* a, uint32_t b0, uint32_t b1) {
    asm volatile(
        "mma.sync.aligned.m16n8k16.row.col.f32.bf16.bf16.f32 "
        "{%0,%1,%2,%3}, {%4,%5,%6,%7}, {%8,%9}, {%0,%1,%2,%3};"
        : "+f"(c[0]), "+f"(c[1]), "+f"(c[2]), "+f"(c[3])
        : "r"(a[0]), "r"(a[1]), "r"(a[2]), "r"(a[3]), "r"(b0), "r"(b1));
}
// Fast SiLU: silu(z) = h + h*tanh(h), h = z/2.  1 MUFU + FMUL + FFMA.
DINL float silu_f(float z) {
    const float h = 0.5f * z;
    float t;
    asm("tanh.approx.f32 %0, %1;" : "=f"(t) : "f"(h));
    return fmaf(h, t, h);
}
DINL uint32_t pack_bf(__nv_bfloat16 a, __nv_bfloat16 b) {
    return (uint32_t)__bfloat16_as_ushort(a)
         | ((uint32_t)__bfloat16_as_ushort(b) << 16);
}
// split two fp32 into packed bf16 hi + residual lo fragments
DINL void split2(float x, float y, uint32_t& hi, uint32_t& lo) {
    const __nv_bfloat16 hx = __float2bfloat16(x);
    const __nv_bfloat16 hy = __float2bfloat16(y);
    hi = pack_bf(hx, hy);
    lo = pack_bf(__float2bfloat16(x - __bfloat162float(hx)),
                 __float2bfloat16(y - __bfloat162float(hy)));
}

// ---------------------------------------------------------------------------
// Prologue GEMM via mma.sync, split-bf16 3-pass (hh, lh, hl).  (validated R14)
// C[m][n] = sum_k A[m*K+k] * B'[n][k] + (n<bias_n ? bias[n] : 0)
//   B'[n][k] = B[(n & 255)*ldb + (n>>8)*hi_off + k]
// ---------------------------------------------------------------------------
static constexpr int PG_PITCH = 144;                    // 9 x 16B, odd -> conflict-free
static constexpr int PG_AHI = 0;
static constexpr int PG_ALO = PG_AHI + 64 * PG_PITCH;   // 9216
static constexpr int PG_BHI = PG_ALO + 64 * PG_PITCH;   // 18432
static constexpr int PG_BLO = PG_BHI + 64 * PG_PITCH;   // 27648
static constexpr int PG_SMEM = PG_BLO + 64 * PG_PITCH;  // 36864 B (static)

__global__ __launch_bounds__(256) void gemm_mma_nt(
    const float* __restrict__ A, const float* __restrict__ B,
    const float* __restrict__ bias, float* __restrict__ C,
    int M, int N, int K, int ldb, int hi_off, int bias_n)
{
    __shared__ __align__(16) char smem[PG_SMEM];
    const uint32_t sb = smem_u32(smem);
    const int t = threadIdx.x;
    const int w = t >> 5;
    const int l = t & 31;
    const int n0 = blockIdx.x * 64;
    const int m0 = blockIdx.y * 64;
    const int wm = w >> 2;          // 0..1  (m32 tile)
    const int wn = w & 3;           // 0..3  (n16 tile)

    const int grp = l >> 3;
    const uint32_t aOffPart =
        (uint32_t)(((grp & 1) * 8 + (l & 7)) * PG_PITCH + (grp >> 1) * 16);
    const uint32_t bOffPart =
        (uint32_t)((wn * 16 + (grp >> 1) * 8 + (l & 7)) * PG_PITCH + (grp & 1) * 16);

    float acc[2][2][4];
#pragma unroll
    for (int mt = 0; mt < 2; ++mt)
#pragma unroll
        for (int nb = 0; nb < 2; ++nb)
#pragma unroll
            for (int q = 0; q < 4; ++q) acc[mt][nb][q] = 0.0f;

    for (int kc = 0; kc < K; kc += 64) {
        if (kc) __syncthreads();
#pragma unroll
        for (int i = 0; i < 4; ++i) {
            const int idx = t + i * 256, r = idx >> 4, c4 = idx & 15;
            const float4 v =
                *(const float4*)(A + (size_t)(m0 + r) * K + kc + c4 * 4);
            uint32_t h0, lo0, h1, lo1;
            split2(v.x, v.y, h0, lo0);
            split2(v.z, v.w, h1, lo1);
            *(uint2*)(smem + PG_AHI + r * PG_PITCH + c4 * 8) = make_uint2(h0, h1);
            *(uint2*)(smem + PG_ALO + r * PG_PITCH + c4 * 8) = make_uint2(lo0, lo1);
        }
#pragma unroll
        for (int i = 0; i < 4; ++i) {
            const int idx = t + i * 256, r = idx >> 4, c4 = idx & 15;
            const int nr = n0 + r;
            const float4 v =
                *(const float4*)(B + (size_t)(nr & 255) * ldb
                                   + (size_t)(nr >> 8) * hi_off + kc + c4 * 4);
            uint32_t h0, lo0, h1, lo1;
            split2(v.x, v.y, h0, lo0);
            split2(v.z, v.w, h1, lo1);
            *(uint2*)(smem + PG_BHI + r * PG_PITCH + c4 * 8) = make_uint2(h0, h1);
            *(uint2*)(smem + PG_BLO + r * PG_PITCH + c4 * 8) = make_uint2(lo0, lo1);
        }
        __syncthreads();

#pragma unroll
        for (int s = 0; s < 4; ++s) {
            const uint32_t kOff = (uint32_t)(s * 32);
            uint32_t bh[4], bl[4];
            ldsm_x4(bh[0], bh[1], bh[2], bh[3], sb + PG_BHI + bOffPart + kOff);
            ldsm_x4(bl[0], bl[1], bl[2], bl[3], sb + PG_BLO + bOffPart + kOff);
#pragma unroll
            for (int mt = 0; mt < 2; ++mt) {
                const uint32_t aRow =
                    (uint32_t)((wm * 32 + mt * 16) * PG_PITCH) + aOffPart + kOff;
                uint32_t ah[4], al[4];
                ldsm_x4(ah[0], ah[1], ah[2], ah[3], sb + PG_AHI + aRow);
                ldsm_x4(al[0], al[1], al[2], al[3], sb + PG_ALO + aRow);
#pragma unroll
                for (int nb = 0; nb < 2; ++nb) {
                    mma16816(acc[mt][nb], ah, bh[2 * nb], bh[2 * nb + 1]);
                    mma16816(acc[mt][nb], al, bh[2 * nb], bh[2 * nb + 1]);
                    mma16816(acc[mt][nb], ah, bl[2 * nb], bl[2 * nb + 1]);
                }
            }
        }
    }

#pragma unroll
    for (int mt = 0; mt < 2; ++mt) {
#pragma unroll
        for (int nb = 0; nb < 2; ++nb) {
            const int n = n0 + wn * 16 + nb * 8 + (l & 3) * 2;
            const float bx = (n     < bias_n) ? bias[n]     : 0.0f;
            const float by = (n + 1 < bias_n) ? bias[n + 1] : 0.0f;
            const int m = m0 + wm * 32 + mt * 16 + (l >> 2);
            *(float2*)(C + (size_t)m * N + n) =
                make_float2(acc[mt][nb][0] + bx, acc[mt][nb][1] + by);
            *(float2*)(C + (size_t)(m + 8) * N + n) =
                make_float2(acc[mt][nb][2] + bx, acc[mt][nb][3] + by);
        }
    }
}

// ---------------------------------------------------------------------------
// W2 hi/lo bf16 split (natural [e][g] layout)
// ---------------------------------------------------------------------------
__global__ void w2split_kernel(const float* __restrict__ W2,
                               __nv_bfloat16* __restrict__ hi,
                               __nv_bfloat16* __restrict__ lo)
{
    const int idx = blockIdx.x * 256 + threadIdx.x;   // 16384
    const float w = W2[idx];
    const __nv_bfloat16 h = __float2bfloat16(w);
    hi[idx] = h;
    lo[idx] = __float2bfloat16(w - __bfloat162float(h));
}

// ---------------------------------------------------------------------------
// Main fused kernel — R11/R14 structure (m32-per-warp), tanh-based SiLU.
// Per CTA: 512 pairs (16 i x 16 j) x 64 e, K=256 as 16 k16-slices.
// ---------------------------------------------------------------------------
static constexpr int W2_PITCH  = 528;
static constexpr int PAB_PITCH = 1040;
static constexpr int OFF_W2HI = 0;
static constexpr int OFF_W2LO = OFF_W2HI + 64 * W2_PITCH;     // 33792
static constexpr int OFF_PA   = OFF_W2LO + 64 * W2_PITCH;     // 67584 (16 rows)
static constexpr int OFF_PB   = OFF_PA + 16 * PAB_PITCH;      // 84224 (16 rows)
static constexpr int SMEM_TOTAL = OFF_PB + 16 * PAB_PITCH;    // 100864 B -> 2 CTAs/SM

__global__ __launch_bounds__(256, 2) void edge_main_mma(
    const float* __restrict__ pab,
    const __nv_bfloat16* __restrict__ W2hi_g,
    const __nv_bfloat16* __restrict__ W2lo_g,
    const float* __restrict__ b2, float* __restrict__ out)
{
    extern __shared__ __align__(16) char smem[];
    const uint32_t sb = smem_u32(smem);
    const int t = threadIdx.x;
    const int w = t >> 5;
    const int l = t & 31;
    const int i0 = blockIdx.x * 16;
    const int j0 = blockIdx.y * 16;
    const int b  = blockIdx.z;

    // ---- stage W2 hi/lo into [e][g] pitch-528 tiles ----
    {
        const uint4* hs = (const uint4*)W2hi_g;   // 2048 uint4 each
        const uint4* ls = (const uint4*)W2lo_g;
#pragma unroll
        for (int i = 0; i < 8; ++i) {
            const int idx = t + i * 256;
            const int row = idx >> 5, c = idx & 31;
            *(uint4*)(smem + OFF_W2HI + row * W2_PITCH + c * 16) = hs[idx];
            *(uint4*)(smem + OFF_W2LO + row * W2_PITCH + c * 16) = ls[idx];
        }
    }
    // ---- stage pa (16 x 256 f32) and pb (16 x 256 f32) ----
#pragma unroll
    for (int i = 0; i < 4; ++i) {
        const int idx = t + i * 256, r = idx >> 6, c4 = idx & 63;
        ((float4*)(smem + OFF_PA + r * PAB_PITCH))[c4] =
            ((const float4*)(pab + (size_t)(b * 256 + i0 + r) * 512))[c4];
    }
#pragma unroll
    for (int i = 0; i < 4; ++i) {
        const int idx = t + i * 256, r = idx >> 6, c4 = idx & 63;
        ((float4*)(smem + OFF_PB + r * PAB_PITCH))[c4] =
            ((const float4*)(pab + (size_t)(b * 256 + j0 + r) * 512 + 256))[c4];
    }
    __syncthreads();   // the ONLY barrier

    const int grp = l >> 2;    // 0..7 (m-row within tile / output j-row)
    const int tig = l & 3;     // thread-in-group (k pair selector)

    const float* paW0 = (const float*)(smem + OFF_PA + w * PAB_PITCH);
    const float* paW1 = (const float*)(smem + OFF_PA + (w + 8) * PAB_PITCH);
    const float* pbR0 = (const float*)(smem + OFF_PB + grp * PAB_PITCH);
    const float* pbR1 = (const float*)(smem + OFF_PB + (grp + 8) * PAB_PITCH);

    // B ldmatrix lane addressing (validated R9-R14)
    const int lg = l >> 3;
    const uint32_t bRowPart =
        (uint32_t)(((lg >> 1) * 8 + (l & 7)) * W2_PITCH + (lg & 1) * 16);
    const uint32_t bHiBase = sb + OFF_W2HI + bRowPart;
    const uint32_t bLoBase = sb + OFF_W2LO + bRowPart;

    float acc0[8][4], acc1[8][4];
#pragma unroll
    for (int n = 0; n < 8; ++n)
#pragma unroll
        for (int q = 0; q < 4; ++q) { acc0[n][q] = 0.0f; acc1[n][q] = 0.0f; }

#pragma unroll 2
    for (int s = 0; s < 16; ++s) {
        const int kb = s * 16 + tig * 2;
        const float2 pb0A = *(const float2*)(pbR0 + kb);
        const float2 pb0B = *(const float2*)(pbR0 + kb + 8);
        const float2 pb1A = *(const float2*)(pbR1 + kb);
        const float2 pb1B = *(const float2*)(pbR1 + kb + 8);

        uint32_t ah0[4], al0[4], ah1[4], al1[4];
        {   // m-tile 0: i = i0 + w
            const float2 paA = *(const float2*)(paW0 + kb);
            const float2 paB = *(const float2*)(paW0 + kb + 8);
            split2(silu_f(paA.x + pb0A.x), silu_f(paA.y + pb0A.y), ah0[0], al0[0]);
            split2(silu_f(paA.x + pb1A.x), silu_f(paA.y + pb1A.y), ah0[1], al0[1]);
            split2(silu_f(paB.x + pb0B.x), silu_f(paB.y + pb0B.y), ah0[2], al0[2]);
            split2(silu_f(paB.x + pb1B.x), silu_f(paB.y + pb1B.y), ah0[3], al0[3]);
        }
        {   // m-tile 1: i = i0 + w + 8
            const float2 paA = *(const float2*)(paW1 + kb);
            const float2 paB = *(const float2*)(paW1 + kb + 8);
            split2(silu_f(paA.x + pb0A.x), silu_f(paA.y + pb0A.y), ah1[0], al1[0]);
            split2(silu_f(paA.x + pb1A.x), silu_f(paA.y + pb1A.y), ah1[1], al1[1]);
            split2(silu_f(paB.x + pb0B.x), silu_f(paB.y + pb0B.y), ah1[2], al1[2]);
            split2(silu_f(paB.x + pb1B.x), silu_f(paB.y + pb1B.y), ah1[3], al1[3]);
        }

        const uint32_t kOff = (uint32_t)(s * 32);
#pragma unroll
        for (int nbp = 0; nbp < 4; ++nbp) {
            const uint32_t eOff = (uint32_t)(nbp * 16 * W2_PITCH);
            uint32_t bh[4], bl[4];
            ldsm_x4(bh[0], bh[1], bh[2], bh[3], bHiBase + eOff + kOff);
            ldsm_x4(bl[0], bl[1], bl[2], bl[3], bLoBase + eOff + kOff);
            mma16816(acc0[2 * nbp],     ah0, bh[0], bh[1]);
            mma16816(acc0[2 * nbp],     al0, bh[0], bh[1]);
            mma16816(acc0[2 * nbp],     ah0, bl[0], bl[1]);
            mma16816(acc0[2 * nbp + 1], ah0, bh[2], bh[3]);
            mma16816(acc0[2 * nbp + 1], al0, bh[2], bh[3]);
            mma16816(acc0[2 * nbp + 1], ah0, bl[2], bl[3]);
            mma16816(acc1[2 * nbp],     ah1, bh[0], bh[1]);
            mma16816(acc1[2 * nbp],     al1, bh[0], bh[1]);
            mma16816(acc1[2 * nbp],     ah1, bl[0], bl[1]);
            mma16816(acc1[2 * nbp + 1], ah1, bh[2], bh[3]);
            mma16816(acc1[2 * nbp + 1], al1, bh[2], bh[3]);
            mma16816(acc1[2 * nbp + 1], ah1, bl[2], bl[3]);
        }
    }

    // ---- epilogue: + b2, direct coalesced stores (4 output rows/thread) ----
    {
        const int ec = tig * 2;
        const size_t row0 = ((size_t)(b * 256 + i0 + w) * 256 + j0 + grp);
        const size_t row1 = ((size_t)(b * 256 + i0 + w + 8) * 256 + j0 + grp);
        float* o0A = out + row0 * 64;
        float* o0B = o0A + 8 * 64;     // grp + 8 along j
        float* o1A = out + row1 * 64;
        float* o1B = o1A + 8 * 64;
#pragma unroll
        for (int nb = 0; nb < 8; ++nb) {
            const int e = nb * 8 + ec;
            const float2 bb = *(const float2*)(b2 + e);
            *(float2*)(o0A + e) = make_float2(acc0[nb][0] + bb.x, acc0[nb][1] + bb.y);
            *(float2*)(o0B + e) = make_float2(acc0[nb][2] + bb.x, acc0[nb][3] + bb.y);
            *(float2*)(o1A + e) = make_float2(acc1[nb][0] + bb.x, acc1[nb][1] + bb.y);
            *(float2*)(o1B + e) = make_float2(acc1[nb][2] + bb.x, acc1[nb][3] + bb.y);
        }
    }
}

// ---------------------------------------------------------------------------
// Launch
// ---------------------------------------------------------------------------
extern "C" void kernel_launch(void* const* d_in, const int* in_sizes, int n_in,
                              void* d_out, int out_size)
{
    (void)in_sizes; (void)n_in; (void)out_size;
    const float* x    = (const float*)d_in[0];
    const float* W_in = (const float*)d_in[1];
    const float* b_in = (const float*)d_in[2];
    const float* W1   = (const float*)d_in[3];
    const float* b1   = (const float*)d_in[4];
    const float* W2   = (const float*)d_in[5];
    const float* b2   = (const float*)d_in[6];
    float* out = (float*)d_out;

    float *hp = nullptr, *pabp = nullptr;
    __nv_bfloat16 *w2hip = nullptr, *w2lop = nullptr;
    cudaGetSymbolAddress((void**)&hp,    g_h);
    cudaGetSymbolAddress((void**)&pabp,  g_pab);
    cudaGetSymbolAddress((void**)&w2hip, g_W2hi);
    cudaGetSymbolAddress((void**)&w2lop, g_W2lo);

    // h = x @ W_in^T + b_in          (64 CTAs, tensor-core)
    gemm_mma_nt<<<dim3(4, 16), 256>>>(x, W_in, b_in, hp,
                                      1024, 256, 256, 256, 0, 256);
    // [pa | pb] = h @ [Wa^T | Wb^T]  (128 CTAs, tensor-core), b1 folded into pa
    gemm_mma_nt<<<dim3(8, 16), 256>>>(hp, W1, b1, pabp,
                                      1024, 512, 256, 512, 256, 256);
    w2split_kernel<<<64, 256>>>(W2, w2hip, w2lop);

    cudaFuncSetAttribute(edge_main_mma,
                         cudaFuncAttributeMaxDynamicSharedMemorySize, SMEM_TOTAL);
    edge_main_mma<<<dim3(16, 16, 4), 256, SMEM_TOTAL>>>(pabp, w2hip, w2lop,
                                                        b2, out);
}

// round 17
// speedup vs baseline: 1.7176x; 1.3294x over previous
#include <cuda_runtime.h>
#include <cuda_bf16.h>
#include <cuda_fp16.h>
#include <cstdint>
#include <cstddef>

// ---------------------------------------------------------------------------
// Scratch (no allocations allowed -> __device__ globals)
// ---------------------------------------------------------------------------
__device__ float g_h[1024 * 256];        // h = x @ W_in^T + b_in
__device__ float g_pab[1024 * 512];      // [pa | pb], b1 folded into pa
__device__ __half g_W2hi[64 * 256];      // fp16 split of W2, natural [e][g]
__device__ __half g_W2lo[64 * 256];

#define DINL __device__ __forceinline__

// ---------------------------------------------------------------------------
// PTX helpers (plain compute_103-safe: no tcgen05)
// ---------------------------------------------------------------------------
DINL uint32_t smem_u32(const void* p) {
    uint32_t a;
    asm("{ .reg .u64 t; cvta.to.shared.u64 t, %1; cvt.u32.u64 %0, t; }"
        : "=r"(a) : "l"(p));
    return a;
}
DINL void ldsm_x4(uint32_t& r0, uint32_t& r1, uint32_t& r2, uint32_t& r3,
                  uint32_t addr) {
    asm volatile("ldmatrix.sync.aligned.m8n8.x4.shared.b16 {%0,%1,%2,%3}, [%4];"
                 : "=r"(r0), "=r"(r1), "=r"(r2), "=r"(r3) : "r"(addr));
}
// bf16 MMA (prologue)
DINL void mma16816(float* c, const uint32_t* a, uint32_t b0, uint32_t b1) {
    asm volatile(
        "mma.sync.aligned.m16n8k16.row.col.f32.bf16.bf16.f32 "
        "{%0,%1,%2,%3}, {%4,%5,%6,%7}, {%8,%9}, {%0,%1,%2,%3};"
        : "+f"(c[0]), "+f"(c[1]), "+f"(c[2]), "+f"(c[3])
        : "r"(a[0]), "r"(a[1]), "r"(a[2]), "r"(a[3]), "r"(b0), "r"(b1));
}
// fp16 MMA (main kernel)
DINL void mma16816h(float* c, const uint32_t* a, uint32_t b0, uint32_t b1) {
    asm volatile(
        "mma.sync.aligned.m16n8k16.row.col.f32.f16.f16.f32 "
        "{%0,%1,%2,%3}, {%4,%5,%6,%7}, {%8,%9}, {%0,%1,%2,%3};"
        : "+f"(c[0]), "+f"(c[1]), "+f"(c[2]), "+f"(c[3])
        : "r"(a[0]), "r"(a[1]), "r"(a[2]), "r"(a[3]), "r"(b0), "r"(b1));
}
// Fast SiLU: silu(z) = h + h*tanh(h), h = z/2.  1 MUFU + FMUL + FFMA.
DINL float silu_f(float z) {
    const float h = 0.5f * z;
    float t;
    asm("tanh.approx.f32 %0, %1;" : "=f"(t) : "f"(h));
    return fmaf(h, t, h);
}
DINL uint32_t pack_bf(__nv_bfloat16 a, __nv_bfloat16 b) {
    return (uint32_t)__bfloat16_as_ushort(a)
         | ((uint32_t)__bfloat16_as_ushort(b) << 16);
}
// split two fp32 into packed bf16 hi + residual lo (prologue)
DINL void split2(float x, float y, uint32_t& hi, uint32_t& lo) {
    const __nv_bfloat16 hx = __float2bfloat16(x);
    const __nv_bfloat16 hy = __float2bfloat16(y);
    hi = pack_bf(hx, hy);
    lo = pack_bf(__float2bfloat16(x - __bfloat162float(hx)),
                 __float2bfloat16(y - __bfloat162float(hy)));
}
// pack two fp32 -> one fp16x2 register (single F2FP)
DINL uint32_t pack_h2(float x, float y) {
    const __half2 h = __floats2half2_rn(x, y);
    return *(const uint32_t*)&h;
}

// ---------------------------------------------------------------------------
// Prologue GEMM via mma.sync, split-bf16 3-pass (validated R14/R15).
// C[m][n] = sum_k A[m*K+k] * B'[n][k] + (n<bias_n ? bias[n] : 0)
//   B'[n][k] = B[(n & 255)*ldb + (n>>8)*hi_off + k]
// ---------------------------------------------------------------------------
static constexpr int PG_PITCH = 144;
static constexpr int PG_AHI = 0;
static constexpr int PG_ALO = PG_AHI + 64 * PG_PITCH;
static constexpr int PG_BHI = PG_ALO + 64 * PG_PITCH;
static constexpr int PG_BLO = PG_BHI + 64 * PG_PITCH;
static constexpr int PG_SMEM = PG_BLO + 64 * PG_PITCH;   // 36864 B

__global__ __launch_bounds__(256) void gemm_mma_nt(
    const float* __restrict__ A, const float* __restrict__ B,
    const float* __restrict__ bias, float* __restrict__ C,
    int M, int N, int K, int ldb, int hi_off, int bias_n)
{
    __shared__ __align__(16) char smem[PG_SMEM];
    const uint32_t sb = smem_u32(smem);
    const int t = threadIdx.x;
    const int w = t >> 5;
    const int l = t & 31;
    const int n0 = blockIdx.x * 64;
    const int m0 = blockIdx.y * 64;
    const int wm = w >> 2;
    const int wn = w & 3;

    const int grp = l >> 3;
    const uint32_t aOffPart =
        (uint32_t)(((grp & 1) * 8 + (l & 7)) * PG_PITCH + (grp >> 1) * 16);
    const uint32_t bOffPart =
        (uint32_t)((wn * 16 + (grp >> 1) * 8 + (l & 7)) * PG_PITCH + (grp & 1) * 16);

    float acc[2][2][4];
#pragma unroll
    for (int mt = 0; mt < 2; ++mt)
#pragma unroll
        for (int nb = 0; nb < 2; ++nb)
#pragma unroll
            for (int q = 0; q < 4; ++q) acc[mt][nb][q] = 0.0f;

    for (int kc = 0; kc < K; kc += 64) {
        if (kc) __syncthreads();
#pragma unroll
        for (int i = 0; i < 4; ++i) {
            const int idx = t + i * 256, r = idx >> 4, c4 = idx & 15;
            const float4 v =
                *(const float4*)(A + (size_t)(m0 + r) * K + kc + c4 * 4);
            uint32_t h0, lo0, h1, lo1;
            split2(v.x, v.y, h0, lo0);
            split2(v.z, v.w, h1, lo1);
            *(uint2*)(smem + PG_AHI + r * PG_PITCH + c4 * 8) = make_uint2(h0, h1);
            *(uint2*)(smem + PG_ALO + r * PG_PITCH + c4 * 8) = make_uint2(lo0, lo1);
        }
#pragma unroll
        for (int i = 0; i < 4; ++i) {
            const int idx = t + i * 256, r = idx >> 4, c4 = idx & 15;
            const int nr = n0 + r;
            const float4 v =
                *(const float4*)(B + (size_t)(nr & 255) * ldb
                                   + (size_t)(nr >> 8) * hi_off + kc + c4 * 4);
            uint32_t h0, lo0, h1, lo1;
            split2(v.x, v.y, h0, lo0);
            split2(v.z, v.w, h1, lo1);
            *(uint2*)(smem + PG_BHI + r * PG_PITCH + c4 * 8) = make_uint2(h0, h1);
            *(uint2*)(smem + PG_BLO + r * PG_PITCH + c4 * 8) = make_uint2(lo0, lo1);
        }
        __syncthreads();

#pragma unroll
        for (int s = 0; s < 4; ++s) {
            const uint32_t kOff = (uint32_t)(s * 32);
            uint32_t bh[4], bl[4];
            ldsm_x4(bh[0], bh[1], bh[2], bh[3], sb + PG_BHI + bOffPart + kOff);
            ldsm_x4(bl[0], bl[1], bl[2], bl[3], sb + PG_BLO + bOffPart + kOff);
#pragma unroll
            for (int mt = 0; mt < 2; ++mt) {
                const uint32_t aRow =
                    (uint32_t)((wm * 32 + mt * 16) * PG_PITCH) + aOffPart + kOff;
                uint32_t ah[4], al[4];
                ldsm_x4(ah[0], ah[1], ah[2], ah[3], sb + PG_AHI + aRow);
                ldsm_x4(al[0], al[1], al[2], al[3], sb + PG_ALO + aRow);
#pragma unroll
                for (int nb = 0; nb < 2; ++nb) {
                    mma16816(acc[mt][nb], ah, bh[2 * nb], bh[2 * nb + 1]);
                    mma16816(acc[mt][nb], al, bh[2 * nb], bh[2 * nb + 1]);
                    mma16816(acc[mt][nb], ah, bl[2 * nb], bl[2 * nb + 1]);
                }
            }
        }
    }

#pragma unroll
    for (int mt = 0; mt < 2; ++mt) {
#pragma unroll
        for (int nb = 0; nb < 2; ++nb) {
            const int n = n0 + wn * 16 + nb * 8 + (l & 3) * 2;
            const float bx = (n     < bias_n) ? bias[n]     : 0.0f;
            const float by = (n + 1 < bias_n) ? bias[n + 1] : 0.0f;
            const int m = m0 + wm * 32 + mt * 16 + (l >> 2);
            *(float2*)(C + (size_t)m * N + n) =
                make_float2(acc[mt][nb][0] + bx, acc[mt][nb][1] + by);
            *(float2*)(C + (size_t)(m + 8) * N + n) =
                make_float2(acc[mt][nb][2] + bx, acc[mt][nb][3] + by);
        }
    }
}

// ---------------------------------------------------------------------------
// W2 fp16 hi/lo split (natural [e][g] layout)
// ---------------------------------------------------------------------------
__global__ void w2split_kernel(const float* __restrict__ W2,
                               __half* __restrict__ hi,
                               __half* __restrict__ lo)
{
    const int idx = blockIdx.x * 256 + threadIdx.x;   // 16384
    const float w = W2[idx];
    const __half h = __float2half_rn(w);
    hi[idx] = h;
    lo[idx] = __float2half_rn(w - __half2float(h));
}

// ---------------------------------------------------------------------------
// Main fused kernel — m32-per-warp (R11 structure), fp16 2-PASS:
//   out = silu_fp16 * (W2hi + W2lo); dropped term = silu fp16-rounding ~2^-12.
// Per CTA: 512 pairs (16 i x 16 j) x 64 e, K=256 as 16 k16-slices.
// Gen per slice: 16 silu + 8 fp16x2 packs (no A-side split).
// ---------------------------------------------------------------------------
static constexpr int W2_PITCH  = 528;
static constexpr int PAB_PITCH = 1040;
static constexpr int OFF_W2HI = 0;
static constexpr int OFF_W2LO = OFF_W2HI + 64 * W2_PITCH;     // 33792
static constexpr int OFF_PA   = OFF_W2LO + 64 * W2_PITCH;     // 67584 (16 rows)
static constexpr int OFF_PB   = OFF_PA + 16 * PAB_PITCH;      // 84224 (16 rows)
static constexpr int SMEM_TOTAL = OFF_PB + 16 * PAB_PITCH;    // 100864 B -> 2 CTAs/SM

__global__ __launch_bounds__(256, 2) void edge_main_mma(
    const float* __restrict__ pab,
    const __half* __restrict__ W2hi_g,
    const __half* __restrict__ W2lo_g,
    const float* __restrict__ b2, float* __restrict__ out)
{
    extern __shared__ __align__(16) char smem[];
    const uint32_t sb = smem_u32(smem);
    const int t = threadIdx.x;
    const int w = t >> 5;
    const int l = t & 31;
    const int i0 = blockIdx.x * 16;
    const int j0 = blockIdx.y * 16;
    const int b  = blockIdx.z;

    // ---- stage W2 hi/lo into [e][g] pitch-528 tiles ----
    {
        const uint4* hs = (const uint4*)W2hi_g;   // 2048 uint4 each
        const uint4* ls = (const uint4*)W2lo_g;
#pragma unroll
        for (int i = 0; i < 8; ++i) {
            const int idx = t + i * 256;
            const int row = idx >> 5, c = idx & 31;
            *(uint4*)(smem + OFF_W2HI + row * W2_PITCH + c * 16) = hs[idx];
            *(uint4*)(smem + OFF_W2LO + row * W2_PITCH + c * 16) = ls[idx];
        }
    }
    // ---- stage pa (16 x 256 f32) and pb (16 x 256 f32) ----
#pragma unroll
    for (int i = 0; i < 4; ++i) {
        const int idx = t + i * 256, r = idx >> 6, c4 = idx & 63;
        ((float4*)(smem + OFF_PA + r * PAB_PITCH))[c4] =
            ((const float4*)(pab + (size_t)(b * 256 + i0 + r) * 512))[c4];
    }
#pragma unroll
    for (int i = 0; i < 4; ++i) {
        const int idx = t + i * 256, r = idx >> 6, c4 = idx & 63;
        ((float4*)(smem + OFF_PB + r * PAB_PITCH))[c4] =
            ((const float4*)(pab + (size_t)(b * 256 + j0 + r) * 512 + 256))[c4];
    }
    __syncthreads();   // the ONLY barrier

    const int grp = l >> 2;    // 0..7 (m-row within tile / output j-row)
    const int tig = l & 3;     // thread-in-group (k pair selector)

    const float* paW0 = (const float*)(smem + OFF_PA + w * PAB_PITCH);
    const float* paW1 = (const float*)(smem + OFF_PA + (w + 8) * PAB_PITCH);
    const float* pbR0 = (const float*)(smem + OFF_PB + grp * PAB_PITCH);
    const float* pbR1 = (const float*)(smem + OFF_PB + (grp + 8) * PAB_PITCH);

    // B ldmatrix lane addressing (validated R9-R15)
    const int lg = l >> 3;
    const uint32_t bRowPart =
        (uint32_t)(((lg >> 1) * 8 + (l & 7)) * W2_PITCH + (lg & 1) * 16);
    const uint32_t bHiBase = sb + OFF_W2HI + bRowPart;
    const uint32_t bLoBase = sb + OFF_W2LO + bRowPart;

    float acc0[8][4], acc1[8][4];
#pragma unroll
    for (int n = 0; n < 8; ++n)
#pragma unroll
        for (int q = 0; q < 4; ++q) { acc0[n][q] = 0.0f; acc1[n][q] = 0.0f; }

#pragma unroll 2
    for (int s = 0; s < 16; ++s) {
        const int kb = s * 16 + tig * 2;
        const float2 pb0A = *(const float2*)(pbR0 + kb);
        const float2 pb0B = *(const float2*)(pbR0 + kb + 8);
        const float2 pb1A = *(const float2*)(pbR1 + kb);
        const float2 pb1B = *(const float2*)(pbR1 + kb + 8);

        uint32_t ah0[4], ah1[4];
        {   // m-tile 0: i = i0 + w   (single fp16 rounding, no split)
            const float2 paA = *(const float2*)(paW0 + kb);
            const float2 paB = *(const float2*)(paW0 + kb + 8);
            ah0[0] = pack_h2(silu_f(paA.x + pb0A.x), silu_f(paA.y + pb0A.y));
            ah0[1] = pack_h2(silu_f(paA.x + pb1A.x), silu_f(paA.y + pb1A.y));
            ah0[2] = pack_h2(silu_f(paB.x + pb0B.x), silu_f(paB.y + pb0B.y));
            ah0[3] = pack_h2(silu_f(paB.x + pb1B.x), silu_f(paB.y + pb1B.y));
        }
        {   // m-tile 1: i = i0 + w + 8
            const float2 paA = *(const float2*)(paW1 + kb);
            const float2 paB = *(const float2*)(paW1 + kb + 8);
            ah1[0] = pack_h2(silu_f(paA.x + pb0A.x), silu_f(paA.y + pb0A.y));
            ah1[1] = pack_h2(silu_f(paA.x + pb1A.x), silu_f(paA.y + pb1A.y));
            ah1[2] = pack_h2(silu_f(paB.x + pb0B.x), silu_f(paB.y + pb0B.y));
            ah1[3] = pack_h2(silu_f(paB.x + pb1B.x), silu_f(paB.y + pb1B.y));
        }

        // ---- B loads + 32 MMAs (2-pass: W2 hi + W2 lo) ----
        const uint32_t kOff = (uint32_t)(s * 32);
#pragma unroll
        for (int nbp = 0; nbp < 4; ++nbp) {
            const uint32_t eOff = (uint32_t)(nbp * 16 * W2_PITCH);
            uint32_t bh[4], bl[4];
            ldsm_x4(bh[0], bh[1], bh[2], bh[3], bHiBase + eOff + kOff);
            ldsm_x4(bl[0], bl[1], bl[2], bl[3], bLoBase + eOff + kOff);
            mma16816h(acc0[2 * nbp],     ah0, bh[0], bh[1]);
            mma16816h(acc0[2 * nbp + 1], ah0, bh[2], bh[3]);
            mma16816h(acc1[2 * nbp],     ah1, bh[0], bh[1]);
            mma16816h(acc1[2 * nbp + 1], ah1, bh[2], bh[3]);
            mma16816h(acc0[2 * nbp],     ah0, bl[0], bl[1]);
            mma16816h(acc0[2 * nbp + 1], ah0, bl[2], bl[3]);
            mma16816h(acc1[2 * nbp],     ah1, bl[0], bl[1]);
            mma16816h(acc1[2 * nbp + 1], ah1, bl[2], bl[3]);
        }
    }

    // ---- epilogue: + b2, direct coalesced stores (4 output rows/thread) ----
    {
        const int ec = tig * 2;
        const size_t row0 = ((size_t)(b * 256 + i0 + w) * 256 + j0 + grp);
        const size_t row1 = ((size_t)(b * 256 + i0 + w + 8) * 256 + j0 + grp);
        float* o0A = out + row0 * 64;
        float* o0B = o0A + 8 * 64;     // grp + 8 along j
        float* o1A = out + row1 * 64;
        float* o1B = o1A + 8 * 64;
#pragma unroll
        for (int nb = 0; nb < 8; ++nb) {
            const int e = nb * 8 + ec;
            const float2 bb = *(const float2*)(b2 + e);
            *(float2*)(o0A + e) = make_float2(acc0[nb][0] + bb.x, acc0[nb][1] + bb.y);
            *(float2*)(o0B + e) = make_float2(acc0[nb][2] + bb.x, acc0[nb][3] + bb.y);
            *(float2*)(o1A + e) = make_float2(acc1[nb][0] + bb.x, acc1[nb][1] + bb.y);
            *(float2*)(o1B + e) = make_float2(acc1[nb][2] + bb.x, acc1[nb][3] + bb.y);
        }
    }
}

// ---------------------------------------------------------------------------
// Launch
// ---------------------------------------------------------------------------
extern "C" void kernel_launch(void* const* d_in, const int* in_sizes, int n_in,
                              void* d_out, int out_size)
{
    (void)in_sizes; (void)n_in; (void)out_size;
    const float* x    = (const float*)d_in[0];
    const float* W_in = (const float*)d_in[1];
    const float* b_in = (const float*)d_in[2];
    const float* W1   = (const float*)d_in[3];
    const float* b1   = (const float*)d_in[4];
    const float* W2   = (const float*)d_in[5];
    const float* b2   = (const float*)d_in[6];
    float* out = (float*)d_out;

    float *hp = nullptr, *pabp = nullptr;
    __half *w2hip = nullptr, *w2lop = nullptr;
    cudaGetSymbolAddress((void**)&hp,    g_h);
    cudaGetSymbolAddress((void**)&pabp,  g_pab);
    cudaGetSymbolAddress((void**)&w2hip, g_W2hi);
    cudaGetSymbolAddress((void**)&w2lop, g_W2lo);

    // h = x @ W_in^T + b_in          (64 CTAs, tensor-core)
    gemm_mma_nt<<<dim3(4, 16), 256>>>(x, W_in, b_in, hp,
                                      1024, 256, 256, 256, 0, 256);
    // [pa | pb] = h @ [Wa^T | Wb^T]  (128 CTAs, tensor-core), b1 folded into pa
    gemm_mma_nt<<<dim3(8, 16), 256>>>(hp, W1, b1, pabp,
                                      1024, 512, 256, 512, 256, 256);
    w2split_kernel<<<64, 256>>>(W2, w2hip, w2lop);

    cudaFuncSetAttribute(edge_main_mma,
                         cudaFuncAttributeMaxDynamicSharedMemorySize, SMEM_TOTAL);
    edge_main_mma<<<dim3(16, 16, 4), 256, SMEM_TOTAL>>>(pabp, w2hip, w2lop,
                                                        b2, out);
}